// round 8
// baseline (speedup 1.0000x reference)
#include <cuda_runtime.h>

// B=16, Wn=64, K=256, E=128, O=64

typedef unsigned long long ull;

__device__ __forceinline__ ull f2_add(ull a, ull b) {
    ull r; asm("add.rn.f32x2 %0,%1,%2;" : "=l"(r) : "l"(a), "l"(b)); return r;
}
__device__ __forceinline__ ull f2_fma(ull a, ull b, ull c) {
    ull r; asm("fma.rn.f32x2 %0,%1,%2,%3;" : "=l"(r) : "l"(a), "l"(b), "l"(c)); return r;
}
__device__ __forceinline__ float f2_hadd(ull a) {
    float lo, hi; asm("mov.b64 {%0,%1},%2;" : "=f"(lo), "=f"(hi) : "l"(a)); return lo + hi;
}
__device__ __forceinline__ ull f2_dup(float v) {
    ull r; asm("mov.b64 %0,{%1,%1};" : "=l"(r) : "f"(v)); return r;
}
__device__ __forceinline__ void f2_unpack(ull a, float& lo, float& hi) {
    asm("mov.b64 {%0,%1},%2;" : "=f"(lo), "=f"(hi) : "l"(a));
}

// Scratch
__device__ float g_L[16 * 256 * 128];
__device__ float g_R[16 * 256 * 128];
__device__ float g_sL[16 * 256];
__device__ float g_sR[16 * 256];

// ---------------------------------------------------------------------------
// k1: C[4096,256] = A[4096,64] x W[256,64]^T ; 4m x 4n register tiles,
// fused sL/sR row-dots via shfl + atomicAdd. grid = 256, 256 threads.
// ---------------------------------------------------------------------------
__global__ void __launch_bounds__(256, 2)
k1_lr(const float* __restrict__ x, const float* __restrict__ lin_w,
      const float* __restrict__ lin_b, const float* __restrict__ a) {
    __shared__ float As[64 * 68];
    __shared__ float Ws[64 * 68];

    int bx = blockIdx.x;
    int mt = bx >> 2, nt = bx & 3;
    int b = mt >> 2, k0 = (mt & 3) * 64;
    int half = nt >> 1, e0 = (nt & 1) * 64;
    int tid = threadIdx.x;

#pragma unroll
    for (int t = 0; t < 4; t++) {
        int idx = t * 256 + tid;
        int w = idx >> 4, m4 = idx & 15;
        float4 v = *reinterpret_cast<const float4*>(x + b * 16384 + w * 256 + k0 + m4 * 4);
        *reinterpret_cast<float4*>(&As[w * 68 + m4 * 4]) = v;
    }
#pragma unroll
    for (int t = 0; t < 4; t++) {
        int idx = t * 256 + tid;
        int n = idx >> 4, w4 = idx & 15;
        float4 v = *reinterpret_cast<const float4*>(lin_w + (e0 + n) * 128 + half * 64 + w4 * 4);
        Ws[(w4 * 4 + 0) * 68 + n] = v.x;
        Ws[(w4 * 4 + 1) * 68 + n] = v.y;
        Ws[(w4 * 4 + 2) * 68 + n] = v.z;
        Ws[(w4 * 4 + 3) * 68 + n] = v.w;
    }
    __syncthreads();

    int mg = tid >> 4, ng = tid & 15;
    ull acc[4][2];
#pragma unroll
    for (int n = 0; n < 4; n++) { acc[n][0] = 0ULL; acc[n][1] = 0ULL; }

#pragma unroll 8
    for (int w = 0; w < 64; w++) {
        const ull* ap = reinterpret_cast<const ull*>(&As[w * 68 + mg * 4]);
        ull a0 = ap[0], a1 = ap[1];
        float4 wn = *reinterpret_cast<const float4*>(&Ws[w * 68 + ng * 4]);
        ull w0 = f2_dup(wn.x), w1 = f2_dup(wn.y), w2 = f2_dup(wn.z), w3 = f2_dup(wn.w);
        acc[0][0] = f2_fma(a0, w0, acc[0][0]); acc[0][1] = f2_fma(a1, w0, acc[0][1]);
        acc[1][0] = f2_fma(a0, w1, acc[1][0]); acc[1][1] = f2_fma(a1, w1, acc[1][1]);
        acc[2][0] = f2_fma(a0, w2, acc[2][0]); acc[2][1] = f2_fma(a1, w2, acc[2][1]);
        acc[3][0] = f2_fma(a0, w3, acc[3][0]); acc[3][1] = f2_fma(a1, w3, acc[3][1]);
    }

    float4 lb4 = make_float4(0.f, 0.f, 0.f, 0.f);
    if (half == 0) lb4 = *reinterpret_cast<const float4*>(lin_b + e0 + ng * 4);
    float4 a6 = *reinterpret_cast<const float4*>(a + e0 + ng * 4);
    a6.x *= 0.6f; a6.y *= 0.6f; a6.z *= 0.6f; a6.w *= 0.6f;

    float* outbase = (half ? g_R : g_L) + (b * 256 + k0 + mg * 4) * 128 + e0 + ng * 4;
    float part[4];
#pragma unroll
    for (int p = 0; p < 2; p++) {
        float lo[4], hi[4];
#pragma unroll
        for (int n = 0; n < 4; n++) f2_unpack(acc[n][p], lo[n], hi[n]);
        float l0 = lo[0] + lb4.x, l1 = lo[1] + lb4.y, l2 = lo[2] + lb4.z, l3 = lo[3] + lb4.w;
        float h0 = hi[0] + lb4.x, h1 = hi[1] + lb4.y, h2 = hi[2] + lb4.z, h3 = hi[3] + lb4.w;
        *reinterpret_cast<float4*>(outbase + (2 * p) * 128) = make_float4(l0, l1, l2, l3);
        *reinterpret_cast<float4*>(outbase + (2 * p + 1) * 128) = make_float4(h0, h1, h2, h3);
        part[2 * p]     = l0 * a6.x + l1 * a6.y + l2 * a6.z + l3 * a6.w;
        part[2 * p + 1] = h0 * a6.x + h1 * a6.y + h2 * a6.z + h3 * a6.w;
    }
#pragma unroll
    for (int o = 8; o > 0; o >>= 1) {
#pragma unroll
        for (int r = 0; r < 4; r++)
            part[r] += __shfl_down_sync(0xffffffffu, part[r], o, 16);
    }
    if (ng == 0) {
        float* sp = (half ? g_sR : g_sL) + b * 256 + k0 + mg * 4;
#pragma unroll
        for (int r = 0; r < 4; r++) atomicAdd(sp + r, part[r]);
    }
}

// ---------------------------------------------------------------------------
// k2: e-scores + softmax + h + fused FC partial.
// grid = 128 (16b x 8 itiles of 32), 512 threads (16 warps), smem 118,528 B.
// e-phase: 512 = 8 ig x 16 jg x 4 e-quarters; 4i x 4j tiles; pairwise fold.
// ---------------------------------------------------------------------------
__global__ void __launch_bounds__(512, 1)
k2_attn(const float* __restrict__ x, const float* __restrict__ bias_kk,
        const float* __restrict__ a, const float* __restrict__ fc_w,
        const float* __restrict__ fc_b, float* __restrict__ out) {
    extern __shared__ float S[];
    const int LS = 0;        // 32 x 132
    const int RS = 4224;     // 64 x 130 (reused: h partials 2x2048; FW at +4096)
    const int ES = 12544;    // 32 x 260  (eh0+eh1 partials -> probs -> HT)
    const int ES2 = 20864;   // 32 x 260  (eh2+eh3 partials)
    const int CS = 29184;    // 128
    const int SRS = 29312;   // 256
    const int SLS = 29568;   // 32
    const int INVS = 29600;  // 32
    const int FW = RS + 4096;   // 64 x 34
    const int HT = ES;          // 64 x 34
    const ull ABSM = 0x7FFFFFFF7FFFFFFFULL;

    int tid = threadIdx.x;
    int b = blockIdx.x >> 3;
    int i0 = (blockIdx.x & 7) << 5;

    const float* Lg = g_L + (b * 256 + i0) * 128;
#pragma unroll
    for (int t = 0; t < 2; t++) {
        int idx = t * 512 + tid;
        int row = idx >> 5, c4 = idx & 31;
        float4 v = *reinterpret_cast<const float4*>(Lg + row * 128 + c4 * 4);
        *reinterpret_cast<float4*>(&S[LS + row * 132 + c4 * 4]) = v;
    }
    if (tid < 128) S[CS + tid] = 0.4f * a[tid];
    if (tid < 256) S[SRS + tid] = g_sR[b * 256 + tid];
    if (tid < 32) S[SLS + tid] = g_sL[b * 256 + i0 + tid];

    int eh = tid >> 7;           // e-quarter 0..3
    int r = tid & 127;
    int ig = r >> 4;             // 0..7 -> i = ig + 8u
    int jg = r & 15;             // 0..15 -> j = jt*64 + jg + 16v
    const ull* Lp0 = reinterpret_cast<const ull*>(&S[LS + (ig) * 132]) + eh * 16;
    const ull* Lp1 = reinterpret_cast<const ull*>(&S[LS + (ig + 8) * 132]) + eh * 16;
    const ull* Lp2 = reinterpret_cast<const ull*>(&S[LS + (ig + 16) * 132]) + eh * 16;
    const ull* Lp3 = reinterpret_cast<const ull*>(&S[LS + (ig + 24) * 132]) + eh * 16;
    const ull* Cp = reinterpret_cast<const ull*>(&S[CS]) + eh * 16;
    float* Eq = (eh & 2) ? &S[ES2] : &S[ES];
    bool writer = (eh & 1) == 0;   // eh 0,2 store; eh 1,3 accumulate

    // prefetch R(jt=0): 2048 float4 / 512 threads = 4 each
    const float* Rg0 = g_R + (b * 256) * 128;
    float4 pf[4];
#pragma unroll
    for (int t = 0; t < 4; t++) {
        int idx = t * 512 + tid;
        int row = idx >> 5, c4 = idx & 31;
        pf[t] = *reinterpret_cast<const float4*>(Rg0 + row * 128 + c4 * 4);
    }

    for (int jt = 0; jt < 4; jt++) {
        __syncthreads();
#pragma unroll
        for (int t = 0; t < 4; t++) {
            int idx = t * 512 + tid;
            int row = idx >> 5, c4 = idx & 31;
            float* d = &S[RS + row * 130 + c4 * 4];
            *reinterpret_cast<float2*>(d) = make_float2(pf[t].x, pf[t].y);
            *reinterpret_cast<float2*>(d + 2) = make_float2(pf[t].z, pf[t].w);
        }
        __syncthreads();

        if (jt < 3) {
            const float* Rgn = g_R + (b * 256 + (jt + 1) * 64) * 128;
#pragma unroll
            for (int t = 0; t < 4; t++) {
                int idx = t * 512 + tid;
                int row = idx >> 5, c4 = idx & 31;
                pf[t] = *reinterpret_cast<const float4*>(Rgn + row * 128 + c4 * 4);
            }
        }

        const ull* Rp0 = reinterpret_cast<const ull*>(&S[RS + (jg) * 130]) + eh * 16;
        const ull* Rp1 = reinterpret_cast<const ull*>(&S[RS + (jg + 16) * 130]) + eh * 16;
        const ull* Rp2 = reinterpret_cast<const ull*>(&S[RS + (jg + 32) * 130]) + eh * 16;
        const ull* Rp3 = reinterpret_cast<const ull*>(&S[RS + (jg + 48) * 130]) + eh * 16;

        ull acc[4][4];
#pragma unroll
        for (int u = 0; u < 4; u++)
#pragma unroll
            for (int v = 0; v < 4; v++) acc[u][v] = 0ULL;

#pragma unroll 4
        for (int ep = 0; ep < 16; ep++) {
            ull c = Cp[ep];
            ull l0 = Lp0[ep], l1 = Lp1[ep], l2 = Lp2[ep], l3 = Lp3[ep];
            ull r0 = Rp0[ep], r1 = Rp1[ep], r2 = Rp2[ep], r3 = Rp3[ep];
            acc[0][0] = f2_fma(f2_add(l0, r0) & ABSM, c, acc[0][0]);
            acc[0][1] = f2_fma(f2_add(l0, r1) & ABSM, c, acc[0][1]);
            acc[0][2] = f2_fma(f2_add(l0, r2) & ABSM, c, acc[0][2]);
            acc[0][3] = f2_fma(f2_add(l0, r3) & ABSM, c, acc[0][3]);
            acc[1][0] = f2_fma(f2_add(l1, r0) & ABSM, c, acc[1][0]);
            acc[1][1] = f2_fma(f2_add(l1, r1) & ABSM, c, acc[1][1]);
            acc[1][2] = f2_fma(f2_add(l1, r2) & ABSM, c, acc[1][2]);
            acc[1][3] = f2_fma(f2_add(l1, r3) & ABSM, c, acc[1][3]);
            acc[2][0] = f2_fma(f2_add(l2, r0) & ABSM, c, acc[2][0]);
            acc[2][1] = f2_fma(f2_add(l2, r1) & ABSM, c, acc[2][1]);
            acc[2][2] = f2_fma(f2_add(l2, r2) & ABSM, c, acc[2][2]);
            acc[2][3] = f2_fma(f2_add(l2, r3) & ABSM, c, acc[2][3]);
            acc[3][0] = f2_fma(f2_add(l3, r0) & ABSM, c, acc[3][0]);
            acc[3][1] = f2_fma(f2_add(l3, r1) & ABSM, c, acc[3][1]);
            acc[3][2] = f2_fma(f2_add(l3, r2) & ABSM, c, acc[3][2]);
            acc[3][3] = f2_fma(f2_add(l3, r3) & ABSM, c, acc[3][3]);
        }

        float vals[16];
#pragma unroll
        for (int u = 0; u < 4; u++)
#pragma unroll
            for (int v = 0; v < 4; v++) vals[u * 4 + v] = f2_hadd(acc[u][v]);

        if (writer) {
#pragma unroll
            for (int u = 0; u < 4; u++) {
                int i = ig + 8 * u;
#pragma unroll
                for (int v = 0; v < 4; v++)
                    Eq[i * 260 + jt * 64 + jg + 16 * v] = vals[u * 4 + v];
            }
        }
        __syncthreads();
        if (!writer) {
#pragma unroll
            for (int u = 0; u < 4; u++) {
                int i = ig + 8 * u;
#pragma unroll
                for (int v = 0; v < 4; v++)
                    Eq[i * 260 + jt * 64 + jg + 16 * v] += vals[u * 4 + v];
            }
        }
    }
    __syncthreads();

    // softmax over j: 16 warps x 2 rows; fold ES+ES2 + linear terms
    int wid = tid >> 5, lane = tid & 31;
#pragma unroll
    for (int s = 0; s < 2; s++) {
        int rr = wid * 2 + s;
        float sl = S[SLS + rr];
        const float* bp = bias_kk + (i0 + rr) * 256;
        float v[8];
        float m = -1e30f;
#pragma unroll
        for (int u = 0; u < 8; u++) {
            int c = u * 32 + lane;
            int o = rr * 260 + c;
            v[u] = S[ES + o] + S[ES2 + o] + sl + S[SRS + c] + bp[c];
            m = fmaxf(m, v[u]);
        }
#pragma unroll
        for (int o = 16; o > 0; o >>= 1) m = fmaxf(m, __shfl_xor_sync(0xffffffffu, m, o));
        float sum = 0.f;
#pragma unroll
        for (int u = 0; u < 8; u++) {
            float p = __expf(v[u] - m);
            S[ES + rr * 260 + u * 32 + lane] = p;
            sum += p;
        }
#pragma unroll
        for (int o = 16; o > 0; o >>= 1) sum += __shfl_xor_sync(0xffffffffu, sum, o);
        if (lane == 0) S[INVS + rr] = 1.f / sum;
    }
    __syncthreads();

    // stage fc_w slice [64 o][32 kk] into FW (2048 / 512 = 4 each)
#pragma unroll
    for (int t = 0; t < 4; t++) {
        int idx = t * 512 + tid;
        int o = idx >> 5, kk = idx & 31;
        S[FW + o * 34 + kk] = fc_w[o * 256 + i0 + kk];
    }

    // h partials: thread = (w in 64, q = j-half, ih = i-quarter); f[8]
    int w = tid & 63;
    int q = (tid >> 6) & 1;
    int ih = tid >> 7;
    {
        ull f[8];
#pragma unroll
        for (int ii = 0; ii < 8; ii++) f[ii] = 0ULL;
        const float* xp = x + b * 16384 + w * 256 + q * 128;
        const float* pbase = &S[ES + (ih * 8) * 260 + q * 128];
        for (int j4 = 0; j4 < 32; j4++) {
            ulonglong2 xq = *reinterpret_cast<const ulonglong2*>(xp + j4 * 4);
#pragma unroll
            for (int ii = 0; ii < 8; ii++) {
                ulonglong2 pq = *reinterpret_cast<const ulonglong2*>(pbase + ii * 260 + j4 * 4);
                f[ii] = f2_fma(xq.x, pq.x, f[ii]);
                f[ii] = f2_fma(xq.y, pq.y, f[ii]);
            }
        }
#pragma unroll
        for (int ii = 0; ii < 8; ii++)
            S[RS + q * 2048 + (ih * 8 + ii) * 64 + w] = f2_hadd(f[ii]);
    }
    __syncthreads();

    // h final: sigmoid, store transposed HT[w][ii] (2048 / 512 = 4 each)
#pragma unroll
    for (int t = 0; t < 4; t++) {
        int idx = t * 512 + tid;
        int ii = idx >> 6, w2 = idx & 63;
        float sum = S[RS + ii * 64 + w2] + S[RS + 2048 + ii * 64 + w2];
        float val = sum * S[INVS + ii];
        S[HT + w2 * 34 + ii] = 1.f / (1.f + __expf(-val));
    }
    __syncthreads();

    // fused FC partial: out[b,w,o] += sum_kk HT[w][kk] * FW[o][kk]
    {
        int og = tid >> 6;   // 0..7 -> o = og*8 .. og*8+7
        const ull* hp = reinterpret_cast<const ull*>(&S[HT + w * 34]);
        ull acc[8];
#pragma unroll
        for (int ol = 0; ol < 8; ol++) acc[ol] = 0ULL;
#pragma unroll 4
        for (int kp = 0; kp < 16; kp++) {
            ull h2 = hp[kp];
#pragma unroll
            for (int ol = 0; ol < 8; ol++) {
                ull fw2 = *reinterpret_cast<const ull*>(&S[FW + (og * 8 + ol) * 34 + kp * 2]);
                acc[ol] = f2_fma(h2, fw2, acc[ol]);
            }
        }
        bool addb = (blockIdx.x & 7) == 0;
        float* op = out + (b * 64 + w) * 64 + og * 8;
#pragma unroll
        for (int ol = 0; ol < 8; ol++) {
            float val = f2_hadd(acc[ol]);
            if (addb) val += fc_b[og * 8 + ol];
            atomicAdd(op + ol, val);
        }
    }
}

// ---------------------------------------------------------------------------
extern "C" void kernel_launch(void* const* d_in, const int* in_sizes, int n_in,
                              void* d_out, int out_size) {
    const float* x       = (const float*)d_in[0];
    const float* lin_w   = (const float*)d_in[1];
    const float* lin_b   = (const float*)d_in[2];
    const float* a       = (const float*)d_in[3];
    const float* bias_kk = (const float*)d_in[4];
    const float* fc_w    = (const float*)d_in[5];
    const float* fc_b    = (const float*)d_in[6];
    float* out = (float*)d_out;

    cudaFuncSetAttribute(k2_attn, cudaFuncAttributeMaxDynamicSharedMemorySize, 118528);

    void* pL = nullptr; void* pR = nullptr;
    cudaGetSymbolAddress(&pL, g_sL);
    cudaGetSymbolAddress(&pR, g_sR);
    cudaMemsetAsync(pL, 0, 16 * 256 * sizeof(float));
    cudaMemsetAsync(pR, 0, 16 * 256 * sizeof(float));
    cudaMemsetAsync(out, 0, (size_t)out_size * sizeof(float));

    k1_lr<<<256, 256>>>(x, lin_w, lin_b, a);
    k2_attn<<<128, 512, 118528>>>(x, bias_kk, a, fc_w, fc_b, out);
}

// round 10
// speedup vs baseline: 1.2353x; 1.2353x over previous
#include <cuda_runtime.h>

// B=16, Wn=64, K=256, E=128, O=64

typedef unsigned long long ull;

__device__ __forceinline__ ull f2_add(ull a, ull b) {
    ull r; asm("add.rn.f32x2 %0,%1,%2;" : "=l"(r) : "l"(a), "l"(b)); return r;
}
__device__ __forceinline__ ull f2_fma(ull a, ull b, ull c) {
    ull r; asm("fma.rn.f32x2 %0,%1,%2,%3;" : "=l"(r) : "l"(a), "l"(b), "l"(c)); return r;
}
__device__ __forceinline__ float f2_hadd(ull a) {
    float lo, hi; asm("mov.b64 {%0,%1},%2;" : "=f"(lo), "=f"(hi) : "l"(a)); return lo + hi;
}
__device__ __forceinline__ ull f2_dup(float v) {
    ull r; asm("mov.b64 %0,{%1,%1};" : "=l"(r) : "f"(v)); return r;
}
__device__ __forceinline__ void f2_unpack(ull a, float& lo, float& hi) {
    asm("mov.b64 {%0,%1},%2;" : "=f"(lo), "=f"(hi) : "l"(a));
}

// Scratch
__device__ float g_L[16 * 256 * 128];
__device__ float g_R[16 * 256 * 128];
__device__ float g_sL[16 * 256];
__device__ float g_sR[16 * 256];
__device__ float g_h[16 * 256 * 64];

// ---------------------------------------------------------------------------
// k1: C[4096,256] = A[4096,64] x W[256,64]^T ; 4m x 4n register tiles,
// fused sL/sR row-dots (scale 0.6) via shfl + atomicAdd. grid 256, 256 thr.
// ---------------------------------------------------------------------------
__global__ void __launch_bounds__(256, 2)
k1_lr(const float* __restrict__ x, const float* __restrict__ lin_w,
      const float* __restrict__ lin_b, const float* __restrict__ a) {
    __shared__ float As[64 * 68];
    __shared__ float Ws[64 * 68];

    int bx = blockIdx.x;
    int mt = bx >> 2, nt = bx & 3;
    int b = mt >> 2, k0 = (mt & 3) * 64;
    int half = nt >> 1, e0 = (nt & 1) * 64;
    int tid = threadIdx.x;

#pragma unroll
    for (int t = 0; t < 4; t++) {
        int idx = t * 256 + tid;
        int w = idx >> 4, m4 = idx & 15;
        float4 v = *reinterpret_cast<const float4*>(x + b * 16384 + w * 256 + k0 + m4 * 4);
        *reinterpret_cast<float4*>(&As[w * 68 + m4 * 4]) = v;
    }
#pragma unroll
    for (int t = 0; t < 4; t++) {
        int idx = t * 256 + tid;
        int n = idx >> 4, w4 = idx & 15;
        float4 v = *reinterpret_cast<const float4*>(lin_w + (e0 + n) * 128 + half * 64 + w4 * 4);
        Ws[(w4 * 4 + 0) * 68 + n] = v.x;
        Ws[(w4 * 4 + 1) * 68 + n] = v.y;
        Ws[(w4 * 4 + 2) * 68 + n] = v.z;
        Ws[(w4 * 4 + 3) * 68 + n] = v.w;
    }
    __syncthreads();

    int mg = tid >> 4, ng = tid & 15;
    ull acc[4][2];
#pragma unroll
    for (int n = 0; n < 4; n++) { acc[n][0] = 0ULL; acc[n][1] = 0ULL; }

#pragma unroll 8
    for (int w = 0; w < 64; w++) {
        const ull* ap = reinterpret_cast<const ull*>(&As[w * 68 + mg * 4]);
        ull a0 = ap[0], a1 = ap[1];
        float4 wn = *reinterpret_cast<const float4*>(&Ws[w * 68 + ng * 4]);
        ull w0 = f2_dup(wn.x), w1 = f2_dup(wn.y), w2 = f2_dup(wn.z), w3 = f2_dup(wn.w);
        acc[0][0] = f2_fma(a0, w0, acc[0][0]); acc[0][1] = f2_fma(a1, w0, acc[0][1]);
        acc[1][0] = f2_fma(a0, w1, acc[1][0]); acc[1][1] = f2_fma(a1, w1, acc[1][1]);
        acc[2][0] = f2_fma(a0, w2, acc[2][0]); acc[2][1] = f2_fma(a1, w2, acc[2][1]);
        acc[3][0] = f2_fma(a0, w3, acc[3][0]); acc[3][1] = f2_fma(a1, w3, acc[3][1]);
    }

    float4 lb4 = make_float4(0.f, 0.f, 0.f, 0.f);
    if (half == 0) lb4 = *reinterpret_cast<const float4*>(lin_b + e0 + ng * 4);
    float4 a6 = *reinterpret_cast<const float4*>(a + e0 + ng * 4);
    a6.x *= 0.6f; a6.y *= 0.6f; a6.z *= 0.6f; a6.w *= 0.6f;

    float* outbase = (half ? g_R : g_L) + (b * 256 + k0 + mg * 4) * 128 + e0 + ng * 4;
    float part[4];
#pragma unroll
    for (int p = 0; p < 2; p++) {
        float lo[4], hi[4];
#pragma unroll
        for (int n = 0; n < 4; n++) f2_unpack(acc[n][p], lo[n], hi[n]);
        float l0 = lo[0] + lb4.x, l1 = lo[1] + lb4.y, l2 = lo[2] + lb4.z, l3 = lo[3] + lb4.w;
        float h0 = hi[0] + lb4.x, h1 = hi[1] + lb4.y, h2 = hi[2] + lb4.z, h3 = hi[3] + lb4.w;
        *reinterpret_cast<float4*>(outbase + (2 * p) * 128) = make_float4(l0, l1, l2, l3);
        *reinterpret_cast<float4*>(outbase + (2 * p + 1) * 128) = make_float4(h0, h1, h2, h3);
        part[2 * p]     = l0 * a6.x + l1 * a6.y + l2 * a6.z + l3 * a6.w;
        part[2 * p + 1] = h0 * a6.x + h1 * a6.y + h2 * a6.z + h3 * a6.w;
    }
#pragma unroll
    for (int o = 8; o > 0; o >>= 1) {
#pragma unroll
        for (int r = 0; r < 4; r++)
            part[r] += __shfl_down_sync(0xffffffffu, part[r], o, 16);
    }
    if (ng == 0) {
        float* sp = (half ? g_sR : g_sL) + b * 256 + k0 + mg * 4;
#pragma unroll
        for (int r = 0; r < 4; r++) atomicAdd(sp + r, part[r]);
    }
}

// ---------------------------------------------------------------------------
// k2: e = sL+sR + sum(0.4a)|L+R| + bias; softmax; h = sigmoid(p @ v).
// grid = 128 (16b x 8 itiles of 32), 256 thr.
// e-phase: 256 = 4 ig x 16 jg x 4 eh; 8i x 4j register tiles;
// 4 separate e-quarter partial buffers (no fold pass). smem 185,088 B.
// ---------------------------------------------------------------------------
__global__ void __launch_bounds__(256, 1)
k2_attn(const float* __restrict__ x, const float* __restrict__ bias_kk,
        const float* __restrict__ a) {
    extern __shared__ float S[];
    const int LS = 0;        // 32 x 132
    const int RS = 4224;     // 64 x 130 (e-phase R tiles; then h partial scratch unused)
    const int E0 = 12544;    // 32 x 260  -> probabilities after softmax
    const int E1 = 20864;    // 32 x 260  -> xs j-half 0 after softmax
    const int E2 = 29184;    // 32 x 260  -> xs j-half 1 after softmax
    const int E3 = 37504;    // 32 x 260
    const int CS = 45824;    // 128 (0.4*a)
    const int SRS = 45952;   // 256
    const int SLS = 46208;   // 32
    const int INVS = 46240;  // 32   (total 46272 floats = 185,088 B)
    const ull ABSM = 0x7FFFFFFF7FFFFFFFULL;

    int tid = threadIdx.x;
    int b = blockIdx.x >> 3;
    int i0 = (blockIdx.x & 7) << 5;

    const float* Lg = g_L + (b * 256 + i0) * 128;
#pragma unroll
    for (int t = 0; t < 4; t++) {
        int idx = t * 256 + tid;
        int row = idx >> 5, c4 = idx & 31;
        float4 v = *reinterpret_cast<const float4*>(Lg + row * 128 + c4 * 4);
        *reinterpret_cast<float4*>(&S[LS + row * 132 + c4 * 4]) = v;
    }
    if (tid < 128) S[CS + tid] = 0.4f * a[tid];
    S[SRS + tid] = g_sR[b * 256 + tid];
    if (tid < 32) S[SLS + tid] = g_sL[b * 256 + i0 + tid];

    int eh = tid >> 6;          // e-quarter 0..3
    int r = tid & 63;
    int ig = r >> 4;            // 0..3 -> rows ig + 4u, u=0..7
    int jg = r & 15;            // 0..15 -> cols jt*64 + jg + 16v, v=0..3
    const ull* Lp[8];
#pragma unroll
    for (int u = 0; u < 8; u++)
        Lp[u] = reinterpret_cast<const ull*>(&S[LS + (ig + 4 * u) * 132]) + eh * 16;
    const ull* Cp = reinterpret_cast<const ull*>(&S[CS]) + eh * 16;
    float* Eq = &S[E0 + eh * 8320];

    // prefetch R(jt=0): 2048 float4 / 256 thr = 8 each
    const float* Rg0 = g_R + (b * 256) * 128;
    float4 pf[8];
#pragma unroll
    for (int t = 0; t < 8; t++) {
        int idx = t * 256 + tid;
        int row = idx >> 5, c4 = idx & 31;
        pf[t] = *reinterpret_cast<const float4*>(Rg0 + row * 128 + c4 * 4);
    }

    for (int jt = 0; jt < 4; jt++) {
        __syncthreads();
#pragma unroll
        for (int t = 0; t < 8; t++) {
            int idx = t * 256 + tid;
            int row = idx >> 5, c4 = idx & 31;
            float* d = &S[RS + row * 130 + c4 * 4];
            *reinterpret_cast<float2*>(d) = make_float2(pf[t].x, pf[t].y);
            *reinterpret_cast<float2*>(d + 2) = make_float2(pf[t].z, pf[t].w);
        }
        __syncthreads();

        if (jt < 3) {
            const float* Rgn = g_R + (b * 256 + (jt + 1) * 64) * 128;
#pragma unroll
            for (int t = 0; t < 8; t++) {
                int idx = t * 256 + tid;
                int row = idx >> 5, c4 = idx & 31;
                pf[t] = *reinterpret_cast<const float4*>(Rgn + row * 128 + c4 * 4);
            }
        }

        const ull* Rp0 = reinterpret_cast<const ull*>(&S[RS + (jg) * 130]) + eh * 16;
        const ull* Rp1 = reinterpret_cast<const ull*>(&S[RS + (jg + 16) * 130]) + eh * 16;
        const ull* Rp2 = reinterpret_cast<const ull*>(&S[RS + (jg + 32) * 130]) + eh * 16;
        const ull* Rp3 = reinterpret_cast<const ull*>(&S[RS + (jg + 48) * 130]) + eh * 16;

        ull acc[8][4];
#pragma unroll
        for (int u = 0; u < 8; u++)
#pragma unroll
            for (int v = 0; v < 4; v++) acc[u][v] = 0ULL;

#pragma unroll 2
        for (int ep = 0; ep < 16; ep++) {
            ull c = Cp[ep];
            ull r0 = Rp0[ep], r1 = Rp1[ep], r2 = Rp2[ep], r3 = Rp3[ep];
#pragma unroll
            for (int u = 0; u < 8; u++) {
                ull l = Lp[u][ep];
                acc[u][0] = f2_fma(f2_add(l, r0) & ABSM, c, acc[u][0]);
                acc[u][1] = f2_fma(f2_add(l, r1) & ABSM, c, acc[u][1]);
                acc[u][2] = f2_fma(f2_add(l, r2) & ABSM, c, acc[u][2]);
                acc[u][3] = f2_fma(f2_add(l, r3) & ABSM, c, acc[u][3]);
            }
        }
#pragma unroll
        for (int u = 0; u < 8; u++) {
            int i = ig + 4 * u;
#pragma unroll
            for (int v = 0; v < 4; v++) {
                int j = jt * 64 + jg + 16 * v;
                Eq[i * 260 + j] = f2_hadd(acc[u][v]);
            }
        }
    }
    __syncthreads();

    // softmax over j: 8 warps x 4 rows; fold 4 e-quarters + linear terms
    int wid = tid >> 5, lane = tid & 31;
#pragma unroll
    for (int s = 0; s < 4; s++) {
        int rr = wid * 4 + s;
        float sl = S[SLS + rr];
        const float* bp = bias_kk + (i0 + rr) * 256;
        float v[8];
        float m = -1e30f;
#pragma unroll
        for (int u = 0; u < 8; u++) {
            int c = u * 32 + lane;
            int o = rr * 260 + c;
            v[u] = S[E0 + o] + S[E1 + o] + S[E2 + o] + S[E3 + o]
                 + sl + S[SRS + c] + bp[c];
            m = fmaxf(m, v[u]);
        }
#pragma unroll
        for (int o = 16; o > 0; o >>= 1) m = fmaxf(m, __shfl_xor_sync(0xffffffffu, m, o));
        float sum = 0.f;
#pragma unroll
        for (int u = 0; u < 8; u++) {
            float p = __expf(v[u] - m);
            S[E0 + rr * 260 + u * 32 + lane] = p;
            sum += p;
        }
#pragma unroll
        for (int o = 16; o > 0; o >>= 1) sum += __shfl_xor_sync(0xffffffffu, sum, o);
        if (lane == 0) S[INVS + rr] = 1.f / sum;
    }
    __syncthreads();

    // stage x tile: j-half 0 -> E1, j-half 1 -> E2 (coalesced float4 LDG)
#pragma unroll
    for (int t = 0; t < 16; t++) {
        int idx = t * 256 + tid;
        int w2 = idx >> 6, jc4 = idx & 63;
        float4 v = *reinterpret_cast<const float4*>(x + b * 16384 + w2 * 256 + jc4 * 4);
        int base = (jc4 < 32) ? E1 : E2;
        float* d = &S[base + w2 * 130 + (jc4 & 31) * 4];
        *reinterpret_cast<float2*>(d) = make_float2(v.x, v.y);
        *reinterpret_cast<float2*>(d + 2) = make_float2(v.z, v.w);
    }
    __syncthreads();

    // h: thread = (w in 64, ih = i-quarter of 8); f[8] over full j
    int w = tid & 63;
    int ih = tid >> 6;
    ull f[8];
#pragma unroll
    for (int ii = 0; ii < 8; ii++) f[ii] = 0ULL;
    const float* pb = &S[E0 + (ih * 8) * 260];
    const ull* xq0 = reinterpret_cast<const ull*>(&S[E1 + w * 130]);
    const ull* xq1 = reinterpret_cast<const ull*>(&S[E2 + w * 130]);
    for (int j4 = 0; j4 < 32; j4++) {
        ull x0 = xq0[j4 * 2], x1 = xq0[j4 * 2 + 1];
#pragma unroll
        for (int ii = 0; ii < 8; ii++) {
            ulonglong2 pq = *reinterpret_cast<const ulonglong2*>(pb + ii * 260 + j4 * 4);
            f[ii] = f2_fma(x0, pq.x, f[ii]);
            f[ii] = f2_fma(x1, pq.y, f[ii]);
        }
    }
    for (int j4 = 0; j4 < 32; j4++) {
        ull x0 = xq1[j4 * 2], x1 = xq1[j4 * 2 + 1];
#pragma unroll
        for (int ii = 0; ii < 8; ii++) {
            ulonglong2 pq = *reinterpret_cast<const ulonglong2*>(pb + ii * 260 + 128 + j4 * 4);
            f[ii] = f2_fma(x0, pq.x, f[ii]);
            f[ii] = f2_fma(x1, pq.y, f[ii]);
        }
    }
#pragma unroll
    for (int ii = 0; ii < 8; ii++) {
        int i = ih * 8 + ii;
        float val = f2_hadd(f[ii]) * S[INVS + i];
        g_h[(b * 256 + i0 + i) * 64 + w] = 1.f / (1.f + __expf(-val));
    }
}

// ---------------------------------------------------------------------------
// k3: out[b,w,o] = sum_k h[b,k,w] fc_w[o,k] + fc_b[o]
// grid = 128 (16b x 8 wtiles of 8), 256 thr, single staging + 1 sync
// ---------------------------------------------------------------------------
__global__ void __launch_bounds__(256, 2)
k3_fc(const float* __restrict__ fc_w, const float* __restrict__ fc_b,
      float* __restrict__ out) {
    extern __shared__ float T[];
    const int FW = 0;       // 64 x 258
    const int HS = 16512;   // 8 x 258

    int bx = blockIdx.x;
    int b = bx >> 3, wq = bx & 7;
    int w0 = wq * 8;
    int tid = threadIdx.x;
    int w8 = tid & 7, og = tid >> 3;

#pragma unroll
    for (int t = 0; t < 16; t++) {
        int idx = t * 256 + tid;
        int row = idx >> 6, c4 = idx & 63;
        float4 v = *reinterpret_cast<const float4*>(fc_w + row * 256 + c4 * 4);
        float* d = &T[FW + row * 258 + c4 * 4];
        *reinterpret_cast<float2*>(d) = make_float2(v.x, v.y);
        *reinterpret_cast<float2*>(d + 2) = make_float2(v.z, v.w);
    }
#pragma unroll
    for (int t = 0; t < 8; t++) {
        int idx = t * 256 + tid;
        int kk = idx >> 3, ww = idx & 7;
        T[HS + ww * 258 + kk] = g_h[(b * 256 + kk) * 64 + w0 + ww];
    }
    __syncthreads();

    const ull* hp = reinterpret_cast<const ull*>(&T[HS + w8 * 258]);
    const ull* f0 = reinterpret_cast<const ull*>(&T[FW + og * 258]);
    const ull* f1 = reinterpret_cast<const ull*>(&T[FW + (og + 32) * 258]);
    ull acc0 = 0ULL, acc1 = 0ULL;
#pragma unroll 16
    for (int kp = 0; kp < 128; kp++) {
        ull h2 = hp[kp];
        acc0 = f2_fma(h2, f0[kp], acc0);
        acc1 = f2_fma(h2, f1[kp], acc1);
    }
    out[(b * 64 + w0 + w8) * 64 + og] = f2_hadd(acc0) + fc_b[og];
    out[(b * 64 + w0 + w8) * 64 + og + 32] = f2_hadd(acc1) + fc_b[og + 32];
}

// ---------------------------------------------------------------------------
extern "C" void kernel_launch(void* const* d_in, const int* in_sizes, int n_in,
                              void* d_out, int out_size) {
    const float* x       = (const float*)d_in[0];
    const float* lin_w   = (const float*)d_in[1];
    const float* lin_b   = (const float*)d_in[2];
    const float* a       = (const float*)d_in[3];
    const float* bias_kk = (const float*)d_in[4];
    const float* fc_w    = (const float*)d_in[5];
    const float* fc_b    = (const float*)d_in[6];
    float* out = (float*)d_out;

    cudaFuncSetAttribute(k2_attn, cudaFuncAttributeMaxDynamicSharedMemorySize, 185088);
    cudaFuncSetAttribute(k3_fc, cudaFuncAttributeMaxDynamicSharedMemorySize, 74304);

    void* pL = nullptr; void* pR = nullptr;
    cudaGetSymbolAddress(&pL, g_sL);
    cudaGetSymbolAddress(&pR, g_sR);
    cudaMemsetAsync(pL, 0, 16 * 256 * sizeof(float));
    cudaMemsetAsync(pR, 0, 16 * 256 * sizeof(float));

    k1_lr<<<256, 256>>>(x, lin_w, lin_b, a);
    k2_attn<<<128, 256, 185088>>>(x, bias_kk, a);
    k3_fc<<<128, 256, 74304>>>(fc_w, fc_b, out);
}